// round 3
// baseline (speedup 1.0000x reference)
#include <cuda_runtime.h>

typedef unsigned long long u64;

#define HN 4096

constexpr int TH = 64;                 // output rows per tile
constexpr int ITERS = TH + 8;          // 72, multiple of 4
constexpr int OUTW = 112;              // valid output cols per warp strip
constexpr int NSTRIPS = (HN + OUTW - 1) / OUTW;   // 37
constexpr int WPB = 4;
constexpr int GRIDX = (NSTRIPS + WPB - 1) / WPB;  // 10
constexpr int GRIDY = HN / TH;         // 64

__device__ double g_acc;   // zero-initialized at module load; finalize re-zeros it

__global__ void finalize_kernel(float* out) {
    double m = g_acc * (1.0 / ((double)HN * (double)HN));
    out[0] = (float)m;
    out[1] = (float)m;
    g_acc = 0.0;           // reset for the next graph replay
}

// ---- packed f32x2 helpers (Blackwell) ----
static __device__ __forceinline__ u64 f2pack(float lo, float hi) {
    u64 r; asm("mov.b64 %0,{%1,%2};" : "=l"(r) : "f"(lo), "f"(hi)); return r;
}
static __device__ __forceinline__ void f2unpack(u64 v, float& lo, float& hi) {
    asm("mov.b64 {%0,%1},%2;" : "=f"(lo), "=f"(hi) : "l"(v));
}
static __device__ __forceinline__ u64 f2add(u64 a, u64 b) {
    u64 r; asm("add.rn.f32x2 %0,%1,%2;" : "=l"(r) : "l"(a), "l"(b)); return r;
}
static __device__ __forceinline__ u64 f2mul(u64 a, u64 b) {
    u64 r; asm("mul.rn.f32x2 %0,%1,%2;" : "=l"(r) : "l"(a), "l"(b)); return r;
}
static __device__ __forceinline__ u64 f2fma(u64 a, u64 b, u64 c) {
    u64 r; asm("fma.rn.f32x2 %0,%1,%2,%3;" : "=l"(r) : "l"(a), "l"(b), "l"(c)); return r;
}
static __device__ __forceinline__ u64 f2neg(u64 a) {       // sign flip -> ALU pipe
    return a ^ 0x8000000080000000ull;
}

__device__ __forceinline__ float4 ld4(const float* p, bool v) {
    float4 r = make_float4(0.f, 0.f, 0.f, 0.f);
    if (v) r = *reinterpret_cast<const float4*>(p);
    return r;
}

// Window sum G[c] = v[c-1]+v[c]+v[c+1]+v[c+2] at this lane's 4 cols (packed pairs).
// A=(v0,v1) B=(v2,v3); vl = left neighbor v3; vr0,vr1 = right neighbor v0,v1.
static __device__ __forceinline__ void hwinP(u64 A, u64 B,
                                             float vl, float v0, float v1, float v2, float v3,
                                             float vr0, float vr1,
                                             u64& GA, u64& GB) {
    u64 P  = f2pack(vl, v0);
    u64 S1 = f2pack(v1, v2);
    u64 S3 = f2pack(v3, vr0);
    u64 S4 = f2pack(vr0, vr1);
    u64 t2 = f2add(S1, B);
    GA = f2add(f2add(P, A), t2);
    GB = f2add(t2, f2add(S3, S4));
}

// products: unpack, fetch boundary PRODUCTS from neighbors, window-sum.
static __device__ __forceinline__ void prodwin(u64 pA, u64 pB, u64& GA, u64& GB) {
    float p0, p1, p2, p3;
    f2unpack(pA, p0, p1);
    f2unpack(pB, p2, p3);
    float pl  = __shfl_up_sync(0xffffffffu, p3, 1);
    float pr0 = __shfl_down_sync(0xffffffffu, p0, 1);
    float pr1 = __shfl_down_sync(0xffffffffu, p1, 1);
    hwinP(pA, pB, pl, p0, p1, p2, p3, pr0, pr1, GA, GB);
}

__global__ void __launch_bounds__(WPB * 32)
xcorr_kernel(const float* __restrict__ X, const float* __restrict__ Y) {
    const int lane = threadIdx.x & 31;
    const int warp = threadIdx.x >> 5;
    const int strip = blockIdx.x * WPB + warp;
    const int ty0 = blockIdx.y * TH;
    const long col0 = (long)strip * OUTW - 8 + 4 * lane;

    const bool ld_ok = (col0 >= 0) && (col0 + 3 < HN);

    float m_[4], mn_[4];
    float msum = 0.f;
#pragma unroll
    for (int k = 0; k < 4; ++k) {
        long c = col0 + k;
        bool inimg = (c >= 0) && (c < HN);
        m_[k] = (lane >= 1 && lane <= 30 && inimg) ? 1.f : 0.f;          // c mask
        float mo = (lane >= 2 && lane <= 29 && inimg) ? 1.f : 0.f;       // output mask
        mn_[k] = -mo;
        msum += mo;
    }
    const u64 mA = f2pack(m_[0], m_[1]), mB = f2pack(m_[2], m_[3]);
    const u64 nA = f2pack(-0.0625f * m_[0], -0.0625f * m_[1]);
    const u64 nB = f2pack(-0.0625f * m_[2], -0.0625f * m_[3]);

    const int i0 = ty0 - 8;   // multiple of 4

    const float* pX = X + col0 + (long)(i0 + 6) * HN;
    const float* pY = Y + col0 + (long)(i0 + 6) * HN;

    bool v4 = ld_ok && (unsigned)(i0 + 4) < HN;
    bool v5 = ld_ok && (unsigned)(i0 + 5) < HN;
    float4 xs0 = ld4(X + col0 + (long)(i0 + 4) * HN, v4);
    float4 ys0 = ld4(Y + col0 + (long)(i0 + 4) * HN, v4);
    float4 xs1 = ld4(X + col0 + (long)(i0 + 5) * HN, v5);
    float4 ys1 = ld4(Y + col0 + (long)(i0 + 5) * HN, v5);

    // state (all packed)
    u64 rxA[2], rxB[2], ryA[2], ryB[2];              // raw rows, 2-slot ring
    u64 hxA[4], hxB[4], hyA[4], hyB[4];              // h-window rings of x,y
    u64 qiA[4], qiB[4], qjA[4], qjB[4], qcA[4], qcB[4]; // h-window rings of products
    u64 VxA = 0, VxB = 0, VyA = 0, VyB = 0;          // rolling 4-row sums (mu*16)
    u64 ViA = 0, ViB = 0, VjA = 0, VjB = 0, VcA = 0, VcB = 0; // rolling sig sums
#pragma unroll
    for (int s = 0; s < 4; ++s) {
        hxA[s] = hxB[s] = hyA[s] = hyB[s] = 0ull;
        qiA[s] = qiB[s] = qjA[s] = qjB[s] = qcA[s] = qcB[s] = 0ull;
    }
    rxA[0] = rxA[1] = rxB[0] = rxB[1] = 0ull;
    ryA[0] = ryA[1] = ryB[0] = ryB[1] = 0ull;

    float acc = 0.f;   // accumulates -sum(L*m); +count added at the end

#define STEP(T, S) do {                                                         \
    const int i = i0 + (T) + (S);                                               \
    float4 xc = xs0; xs0 = xs1;                                                 \
    float4 yc = ys0; ys0 = ys1;                                                 \
    {   bool v = ld_ok && (unsigned)(i + 6) < HN;                               \
        xs1 = ld4(pX, v); ys1 = ld4(pY, v); pX += HN; pY += HN; }               \
    float xl  = __shfl_up_sync(0xffffffffu, xc.w, 1);                           \
    float xr0 = __shfl_down_sync(0xffffffffu, xc.x, 1);                         \
    float xr1 = __shfl_down_sync(0xffffffffu, xc.y, 1);                         \
    float yl  = __shfl_up_sync(0xffffffffu, yc.w, 1);                           \
    float yr0 = __shfl_down_sync(0xffffffffu, yc.x, 1);                         \
    float yr1 = __shfl_down_sync(0xffffffffu, yc.y, 1);                         \
    /* read raw row i+2 (stored 2 steps ago), then overwrite slot with i+4 */   \
    u64 x2A = rxA[(S) & 1], x2B = rxB[(S) & 1];                                 \
    u64 y2A = ryA[(S) & 1], y2B = ryB[(S) & 1];                                 \
    u64 xAn = f2pack(xc.x, xc.y), xBn = f2pack(xc.z, xc.w);                     \
    u64 yAn = f2pack(yc.x, yc.y), yBn = f2pack(yc.z, yc.w);                     \
    rxA[(S) & 1] = xAn; rxB[(S) & 1] = xBn;                                     \
    ryA[(S) & 1] = yAn; ryB[(S) & 1] = yBn;                                     \
    /* horizontal windows of raw row i+4, rolling vertical (rows i+1..i+4) */   \
    u64 gA, gB;                                                                 \
    hwinP(xAn, xBn, xl, xc.x, xc.y, xc.z, xc.w, xr0, xr1, gA, gB);              \
    VxA = f2add(f2add(VxA, f2neg(hxA[(S)])), gA); hxA[(S)] = gA;                \
    VxB = f2add(f2add(VxB, f2neg(hxB[(S)])), gB); hxB[(S)] = gB;                \
    hwinP(yAn, yBn, yl, yc.x, yc.y, yc.z, yc.w, yr0, yr1, gA, gB);              \
    VyA = f2add(f2add(VyA, f2neg(hyA[(S)])), gA); hyA[(S)] = gA;                \
    VyB = f2add(f2add(VyB, f2neg(hyB[(S)])), gB); hyB[(S)] = gB;                \
    /* centered values at row i+2: c = x*m - V*(m/16), zero outside image */    \
    u64 rm = ((unsigned)(i + 2) < HN) ? ~0ull : 0ull;                           \
    u64 c1A = f2fma(VxA, nA, f2mul(x2A, mA)) & rm;                              \
    u64 c1B = f2fma(VxB, nB, f2mul(x2B, mB)) & rm;                              \
    u64 c2A = f2fma(VyA, nA, f2mul(y2A, mA)) & rm;                              \
    u64 c2B = f2fma(VyB, nB, f2mul(y2B, mB)) & rm;                              \
    /* products, their windows, rolling sig sums (rows i-1..i+2) */             \
    u64 pA, pB;                                                                 \
    pA = f2mul(c1A, c1A); pB = f2mul(c1B, c1B);                                 \
    prodwin(pA, pB, gA, gB);                                                    \
    ViA = f2add(f2add(ViA, f2neg(qiA[((S)+2)&3])), gA); qiA[((S)+2)&3] = gA;    \
    ViB = f2add(f2add(ViB, f2neg(qiB[((S)+2)&3])), gB); qiB[((S)+2)&3] = gB;    \
    pA = f2mul(c2A, c2A); pB = f2mul(c2B, c2B);                                 \
    prodwin(pA, pB, gA, gB);                                                    \
    VjA = f2add(f2add(VjA, f2neg(qjA[((S)+2)&3])), gA); qjA[((S)+2)&3] = gA;    \
    VjB = f2add(f2add(VjB, f2neg(qjB[((S)+2)&3])), gB); qjB[((S)+2)&3] = gB;    \
    pA = f2mul(c1A, c2A); pB = f2mul(c1B, c2B);                                 \
    prodwin(pA, pB, gA, gB);                                                    \
    VcA = f2add(f2add(VcA, f2neg(qcA[((S)+2)&3])), gA); qcA[((S)+2)&3] = gA;    \
    VcB = f2add(f2add(VcB, f2neg(qcB[((S)+2)&3])), gB); qcB[((S)+2)&3] = gB;    \
    if ((T) + (S) >= 8) {  /* output row i */                                   \
        float si0, si1, si2, si3, sj0, sj1, sj2, sj3, sc0, sc1, sc2, sc3;       \
        f2unpack(ViA, si0, si1); f2unpack(ViB, si2, si3);                       \
        f2unpack(VjA, sj0, sj1); f2unpack(VjB, sj2, sj3);                       \
        f2unpack(VcA, sc0, sc1); f2unpack(VcB, sc2, sc3);                       \
        { float a = fmaxf(si0, 1e-20f), b = fmaxf(sj0, 1e-20f);                 \
          float L = sc0 * rsqrtf(a * b); L = fmaxf(L, -1.f);                    \
          acc = fmaf(L, mn_[0], acc); }                                         \
        { float a = fmaxf(si1, 1e-20f), b = fmaxf(sj1, 1e-20f);                 \
          float L = sc1 * rsqrtf(a * b); L = fmaxf(L, -1.f);                    \
          acc = fmaf(L, mn_[1], acc); }                                         \
        { float a = fmaxf(si2, 1e-20f), b = fmaxf(sj2, 1e-20f);                 \
          float L = sc2 * rsqrtf(a * b); L = fmaxf(L, -1.f);                    \
          acc = fmaf(L, mn_[2], acc); }                                         \
        { float a = fmaxf(si3, 1e-20f), b = fmaxf(sj3, 1e-20f);                 \
          float L = sc3 * rsqrtf(a * b); L = fmaxf(L, -1.f);                    \
          acc = fmaf(L, mn_[3], acc); }                                         \
    }                                                                           \
} while (0)

#pragma unroll 1
    for (int T = 0; T < ITERS; T += 4) {
        STEP(T, 0);
        STEP(T, 1);
        STEP(T, 2);
        STEP(T, 3);
    }
#undef STEP

    // total contribution = TH*msum (the +1 per valid pixel) + acc (the -L part)
    float tot = fmaf((float)TH, msum, acc);

#pragma unroll
    for (int o = 16; o; o >>= 1) tot += __shfl_xor_sync(0xffffffffu, tot, o);

    __shared__ float wsum[WPB];
    if (lane == 0) wsum[warp] = tot;
    __syncthreads();
    if (threadIdx.x == 0) {
        float s = 0.f;
#pragma unroll
        for (int w2 = 0; w2 < WPB; ++w2) s += wsum[w2];
        atomicAdd(&g_acc, (double)s);
    }
}

extern "C" void kernel_launch(void* const* d_in, const int* in_sizes, int n_in,
                              void* d_out, int out_size) {
    const float* X = (const float*)d_in[0];   // outputs
    const float* Y = (const float*)d_in[1];   // labels

    dim3 grid(GRIDX, GRIDY);
    xcorr_kernel<<<grid, WPB * 32>>>(X, Y);
    finalize_kernel<<<1, 1>>>((float*)d_out);
}

// round 5
// speedup vs baseline: 1.3341x; 1.3341x over previous
#include <cuda_runtime.h>

#define HN 4096

constexpr int TH = 64;                    // output rows per warp-tile
constexpr int ITERS = TH + 8;             // 72 steps incl. warmup
constexpr int OUTW = 112;                 // output cols per warp strip
constexpr int NSTRIPS = 37;               // 37*112 = 4144 >= 4096
constexpr int WPB = 4;
constexpr int NTILES = NSTRIPS * (HN / TH);   // 2368
constexpr int NBLK = NTILES / WPB;            // 592 = 4 * 148

__device__ double g_acc;       // zero at load; last block resets after use
__device__ unsigned g_done;

__device__ __forceinline__ float4 ld4(const float* p, bool v) {
    float4 r = make_float4(0.f, 0.f, 0.f, 0.f);
    if (v) r = *reinterpret_cast<const float4*>(p);
    return r;
}

// 4-tap window sum over columns: g[c] = v[c-1]+v[c]+v[c+1]+v[c+2]
// vl = left neighbor .w, vr0/vr1 = right neighbor .x/.y
__device__ __forceinline__ float4 hwin(float4 v, float vl, float vr0, float vr1) {
    float4 g;
    g.x = vl + v.x + v.y + v.z;
    g.y = g.x - vl + v.w;
    g.z = g.y - v.x + vr0;
    g.w = g.z - v.y + vr1;
    return g;
}

__global__ void __launch_bounds__(WPB * 32)
xcorr_kernel(const float* __restrict__ X, const float* __restrict__ Y,
             float* __restrict__ out) {
    const int lane = threadIdx.x & 31;
    const int warp = threadIdx.x >> 5;
    const int tile = blockIdx.x * WPB + warp;       // 0..2367, none masked
    const int strip = tile % NSTRIPS;
    const int tyt  = tile / NSTRIPS;                // 0..63
    const int ty0 = tyt * TH;
    const long col0 = (long)strip * OUTW - 8 + 4 * lane;

    const bool ld_ok = (col0 >= 0) && (col0 + 3 < HN);
    const float mC = (lane >= 1 && lane <= 30 && ld_ok) ? 1.f : 0.f;   // c mask
    const float mO = (lane >= 2 && lane <= 29 && ld_ok) ? 1.f : 0.f;   // out mask
    const float mOn = -mO;

    const int i0 = ty0 - 8;    // multiple of 4

    const float* pX = X + col0 + (long)(i0 + 6) * HN;
    const float* pY = Y + col0 + (long)(i0 + 6) * HN;

    bool v4 = ld_ok && (unsigned)(i0 + 4) < HN;
    bool v5 = ld_ok && (unsigned)(i0 + 5) < HN;
    float4 xs0 = ld4(X + col0 + (long)(i0 + 4) * HN, v4);
    float4 ys0 = ld4(Y + col0 + (long)(i0 + 4) * HN, v4);
    float4 xs1 = ld4(X + col0 + (long)(i0 + 5) * HN, v5);
    float4 ys1 = ld4(Y + col0 + (long)(i0 + 5) * HN, v5);

    // state
    float4 rx[4], ry[4];                 // raw row ring (slot = row & 3)
    float4 ri[4], rj[4], rc[4];          // raw product ring (slot = row & 3)
    float4 Vx, Vy;                       // rolling vertical sums of raw (rows i+1..i+4)
    float4 Vi, Vj, Vc;                   // rolling vertical sums of products (rows i-1..i+2)
    {
        float4 z = make_float4(0.f, 0.f, 0.f, 0.f);
#pragma unroll
        for (int s = 0; s < 4; ++s) { rx[s] = z; ry[s] = z; ri[s] = z; rj[s] = z; rc[s] = z; }
        Vx = z; Vy = z; Vi = z; Vj = z; Vc = z;
    }

    float acc = 0.f;   // accumulates -L * mO over output pixels

#define ROLL4(V, RING, P) do {                                   \
    float4 _o = RING; RING = (P);                                \
    V.x += (P).x - _o.x; V.y += (P).y - _o.y;                    \
    V.z += (P).z - _o.z; V.w += (P).w - _o.w;                    \
} while (0)

#define STEP(T, S) do {                                                          \
    const int i = i0 + (T) + (S);                                                \
    float4 xc = xs0; xs0 = xs1;                                                  \
    float4 yc = ys0; ys0 = ys1;                                                  \
    {   bool v = ld_ok && (unsigned)(i + 6) < HN;                                \
        xs1 = ld4(pX, v); ys1 = ld4(pY, v); pX += HN; pY += HN; }                \
    /* rolling vertical raw sums: +row(i+4), -row(i); slot S holds row i */      \
    ROLL4(Vx, rx[(S)], xc);                                                      \
    ROLL4(Vy, ry[(S)], yc);                                                      \
    /* raw row i+2 from ring */                                                  \
    float4 x2 = rx[((S) + 2) & 3], y2 = ry[((S) + 2) & 3];                       \
    /* horizontal window of vertical sums -> 16*mu at row i+2 */                 \
    float vlx  = __shfl_up_sync(0xffffffffu, Vx.w, 1);                           \
    float vrx0 = __shfl_down_sync(0xffffffffu, Vx.x, 1);                         \
    float vrx1 = __shfl_down_sync(0xffffffffu, Vx.y, 1);                         \
    float vly  = __shfl_up_sync(0xffffffffu, Vy.w, 1);                           \
    float vry0 = __shfl_down_sync(0xffffffffu, Vy.x, 1);                         \
    float vry1 = __shfl_down_sync(0xffffffffu, Vy.y, 1);                         \
    float4 mx = hwin(Vx, vlx, vrx0, vrx1);                                       \
    float4 my = hwin(Vy, vly, vry0, vry1);                                       \
    /* centered values at row i+2 */                                             \
    float rowm = ((unsigned)(i + 2) < HN) ? mC : 0.f;                            \
    float4 c1, c2;                                                               \
    c1.x = fmaf(mx.x, -0.0625f, x2.x) * rowm;                                    \
    c1.y = fmaf(mx.y, -0.0625f, x2.y) * rowm;                                    \
    c1.z = fmaf(mx.z, -0.0625f, x2.z) * rowm;                                    \
    c1.w = fmaf(mx.w, -0.0625f, x2.w) * rowm;                                    \
    c2.x = fmaf(my.x, -0.0625f, y2.x) * rowm;                                    \
    c2.y = fmaf(my.y, -0.0625f, y2.y) * rowm;                                    \
    c2.z = fmaf(my.z, -0.0625f, y2.z) * rowm;                                    \
    c2.w = fmaf(my.w, -0.0625f, y2.w) * rowm;                                    \
    /* raw products, rolling vertical sig sums: +row(i+2), -row(i-2) */          \
    float4 p;                                                                    \
    p.x = c1.x * c1.x; p.y = c1.y * c1.y; p.z = c1.z * c1.z; p.w = c1.w * c1.w;  \
    ROLL4(Vi, ri[((S) + 2) & 3], p);                                             \
    p.x = c2.x * c2.x; p.y = c2.y * c2.y; p.z = c2.z * c2.z; p.w = c2.w * c2.w;  \
    ROLL4(Vj, rj[((S) + 2) & 3], p);                                             \
    p.x = c1.x * c2.x; p.y = c1.y * c2.y; p.z = c1.z * c2.z; p.w = c1.w * c2.w;  \
    ROLL4(Vc, rc[((S) + 2) & 3], p);                                             \
    if ((T) + (S) >= 8) {  /* output row i: horizontal windows of sig sums */    \
        float al  = __shfl_up_sync(0xffffffffu, Vi.w, 1);                        \
        float ar0 = __shfl_down_sync(0xffffffffu, Vi.x, 1);                      \
        float ar1 = __shfl_down_sync(0xffffffffu, Vi.y, 1);                      \
        float bl  = __shfl_up_sync(0xffffffffu, Vj.w, 1);                        \
        float br0 = __shfl_down_sync(0xffffffffu, Vj.x, 1);                      \
        float br1 = __shfl_down_sync(0xffffffffu, Vj.y, 1);                      \
        float cl  = __shfl_up_sync(0xffffffffu, Vc.w, 1);                        \
        float cr0 = __shfl_down_sync(0xffffffffu, Vc.x, 1);                      \
        float cr1 = __shfl_down_sync(0xffffffffu, Vc.y, 1);                      \
        float4 sii = hwin(Vi, al, ar0, ar1);                                     \
        float4 sjj = hwin(Vj, bl, br0, br1);                                     \
        float4 sij = hwin(Vc, cl, cr0, cr1);                                     \
        { float a = fmaxf(sii.x, 1e-20f), b = fmaxf(sjj.x, 1e-20f);              \
          float L = fmaxf(sij.x * rsqrtf(a * b), -1.f);                          \
          acc = fmaf(L, mOn, acc); }                                             \
        { float a = fmaxf(sii.y, 1e-20f), b = fmaxf(sjj.y, 1e-20f);              \
          float L = fmaxf(sij.y * rsqrtf(a * b), -1.f);                          \
          acc = fmaf(L, mOn, acc); }                                             \
        { float a = fmaxf(sii.z, 1e-20f), b = fmaxf(sjj.z, 1e-20f);              \
          float L = fmaxf(sij.z * rsqrtf(a * b), -1.f);                          \
          acc = fmaf(L, mOn, acc); }                                             \
        { float a = fmaxf(sii.w, 1e-20f), b = fmaxf(sjj.w, 1e-20f);              \
          float L = fmaxf(sij.w * rsqrtf(a * b), -1.f);                          \
          acc = fmaf(L, mOn, acc); }                                             \
    }                                                                            \
} while (0)

#pragma unroll 1
    for (int T = 0; T < ITERS; T += 4) {
        STEP(T, 0);
        STEP(T, 1);
        STEP(T, 2);
        STEP(T, 3);
    }
#undef STEP
#undef ROLL4

    // per-warp total: count (TH rows * 4*mO cols) + accumulated (-L)
    float tot = fmaf((float)(TH * 4), mO, acc);

#pragma unroll
    for (int o = 16; o; o >>= 1) tot += __shfl_xor_sync(0xffffffffu, tot, o);

    __shared__ float wsum[WPB];
    if (lane == 0) wsum[warp] = tot;
    __syncthreads();
    if (threadIdx.x == 0) {
        float s = wsum[0] + wsum[1] + wsum[2] + wsum[3];
        atomicAdd(&g_acc, (double)s);
        __threadfence();
        unsigned t = atomicAdd(&g_done, 1u);
        if (t == (unsigned)(NBLK - 1)) {          // last block finalizes
            double m = g_acc * (1.0 / ((double)HN * (double)HN));
            out[0] = (float)m;
            out[1] = (float)m;
            g_acc = 0.0;                          // reset for next replay
            g_done = 0u;
        }
    }
}

extern "C" void kernel_launch(void* const* d_in, const int* in_sizes, int n_in,
                              void* d_out, int out_size) {
    const float* X = (const float*)d_in[0];   // outputs
    const float* Y = (const float*)d_in[1];   // labels
    xcorr_kernel<<<NBLK, WPB * 32>>>(X, Y, (float*)d_out);
}